// round 1
// baseline (speedup 1.0000x reference)
#include <cuda_runtime.h>
#include <math.h>

#define NT 16384      // tokens = 4 * 4096
#define DM 1024       // d_model
#define FF 1024       // d_out
#define NE 8          // experts
#define BM 64
#define BN 64
#define BK 16

// ---- device scratch (static, allocation-free) ----
__device__ int   g_cnt[NE];
__device__ int   g_list[NE][NT];        // packed: token | (slot<<16)
__device__ float g_w[2][NT];            // gate weight per slot per token
__device__ float g_scr[2][NT][FF];      // per-slot expert outputs (128 MiB)

__global__ void zero_cnt_kernel() {
    if (threadIdx.x < NE) g_cnt[threadIdx.x] = 0;
}

// One warp per token: 8 dots of length 1024, warp-reduce, top-2, sigmoid, scatter.
__global__ void gate_kernel(const float* __restrict__ x,
                            const float* __restrict__ Wg,
                            const float* __restrict__ bg) {
    int gwarp = (blockIdx.x * blockDim.x + threadIdx.x) >> 5;
    int lane  = threadIdx.x & 31;
    if (gwarp >= NT) return;

    const float* xr = x + (size_t)gwarp * DM;
    float xv[32];
#pragma unroll
    for (int i = 0; i < 32; i++) xv[i] = xr[lane + 32 * i];

    float logits[NE];
#pragma unroll
    for (int e = 0; e < NE; e++) {
        const float* wg = Wg + e * DM;
        float acc = 0.f;
#pragma unroll
        for (int i = 0; i < 32; i++) acc += xv[i] * wg[lane + 32 * i];
#pragma unroll
        for (int o = 16; o > 0; o >>= 1) acc += __shfl_xor_sync(0xffffffffu, acc, o);
        logits[e] = acc + bg[e];
    }

    if (lane == 0) {
        // top-1 (strict >, so lowest index on ties, matching jax top_k)
        int b0 = 0; float v0 = logits[0];
#pragma unroll
        for (int e = 1; e < NE; e++) if (logits[e] > v0) { v0 = logits[e]; b0 = e; }
        int b1 = -1; float v1 = -INFINITY;
#pragma unroll
        for (int e = 0; e < NE; e++) if (e != b0 && logits[e] > v1) { v1 = logits[e]; b1 = e; }

        float w0 = 1.f / (1.f + expf(-v0));
        float w1 = 1.f / (1.f + expf(-v1));
        g_w[0][gwarp] = w0;
        g_w[1][gwarp] = w1;

        int p0 = atomicAdd(&g_cnt[b0], 1);
        g_list[b0][p0] = gwarp;               // slot 0
        int p1 = atomicAdd(&g_cnt[b1], 1);
        g_list[b1][p1] = gwarp | (1 << 16);   // slot 1
    }
}

// Per-expert gathered GEMM: tile BM x BN, fp32, 256 threads, 4x4 microtile.
// grid = (ceil(NT/BM), FF/BN, NE); blocks past this expert's count exit early.
__global__ __launch_bounds__(256) void expert_gemm(const float* __restrict__ x,
                                                   const float* __restrict__ We,
                                                   const float* __restrict__ be) {
    int e   = blockIdx.z;
    int cnt = g_cnt[e];
    int m0  = blockIdx.x * BM;
    if (m0 >= cnt) return;
    int n0  = blockIdx.y * BN;

    __shared__ float As[BK][BM + 1];   // +1 pad: conflict-free scatter-store
    __shared__ float Bs[BK][BN];
    __shared__ int   s_tok[BM];
    __shared__ int   s_slot[BM];
    __shared__ float s_w[BM];

    int tid = threadIdx.x;

    if (tid < BM) {
        int mi = m0 + tid;
        int entry = (mi < cnt) ? g_list[e][mi] : 0;
        s_tok[tid]  = entry & 0xFFFF;
        s_slot[tid] = entry >> 16;
        s_w[tid]    = g_w[entry >> 16][entry & 0xFFFF];
    }
    __syncthreads();

    int tx = tid & 15;    // N direction: cols tx*4 .. tx*4+3
    int ty = tid >> 4;    // M direction: rows ty*4 .. ty*4+3
    float acc[4][4] = {};

    const float* Wb = We + (size_t)e * DM * FF;

    // A-load mapping: 4 threads per row, float4 each (16 floats/row)
    int ar  = tid >> 2;
    int ac4 = (tid & 3) * 4;
    // B-load mapping: 16 threads per k-row, float4 each (64 floats/row)
    int br  = tid >> 4;
    int bc4 = (tid & 15) * 4;

    for (int k0 = 0; k0 < DM; k0 += BK) {
        // gather A tile: BM tokens x BK
        {
            const float* xp = x + (size_t)s_tok[ar] * DM + k0 + ac4;
            float4 v = *(const float4*)xp;
            As[ac4 + 0][ar] = v.x;
            As[ac4 + 1][ar] = v.y;
            As[ac4 + 2][ar] = v.z;
            As[ac4 + 3][ar] = v.w;
        }
        // load B tile: BK x BN from We[e][k0+br][n0+bc4..]
        {
            const float* wp = Wb + (size_t)(k0 + br) * FF + n0 + bc4;
            float4 v = *(const float4*)wp;
            *(float4*)&Bs[br][bc4] = v;
        }
        __syncthreads();

#pragma unroll
        for (int kk = 0; kk < BK; kk++) {
            float a[4], b[4];
#pragma unroll
            for (int i = 0; i < 4; i++) a[i] = As[kk][ty * 4 + i];
#pragma unroll
            for (int j = 0; j < 4; j++) b[j] = Bs[kk][tx * 4 + j];
#pragma unroll
            for (int i = 0; i < 4; i++)
#pragma unroll
                for (int j = 0; j < 4; j++) acc[i][j] += a[i] * b[j];
        }
        __syncthreads();
    }

    float bias[4];
#pragma unroll
    for (int j = 0; j < 4; j++) bias[j] = be[e * FF + n0 + tx * 4 + j];

#pragma unroll
    for (int i = 0; i < 4; i++) {
        int mi = m0 + ty * 4 + i;
        if (mi < cnt) {
            int   tok  = s_tok[ty * 4 + i];
            int   slot = s_slot[ty * 4 + i];
            float w    = s_w[ty * 4 + i];
            float4 o;
            o.x = (acc[i][0] + bias[0]) * w;
            o.y = (acc[i][1] + bias[1]) * w;
            o.z = (acc[i][2] + bias[2]) * w;
            o.w = (acc[i][3] + bias[3]) * w;
            *(float4*)&g_scr[slot][tok][n0 + tx * 4] = o;
        }
    }
}

// out = scr[0] + scr[1]
__global__ void combine_kernel(float* __restrict__ out) {
    size_t j = (size_t)blockIdx.x * blockDim.x + threadIdx.x;  // one float4 each
    const float4* a = (const float4*)g_scr[0];
    const float4* b = (const float4*)g_scr[1];
    float4 u = a[j], v = b[j];
    ((float4*)out)[j] = make_float4(u.x + v.x, u.y + v.y, u.z + v.z, u.w + v.w);
}

extern "C" void kernel_launch(void* const* d_in, const int* in_sizes, int n_in,
                              void* d_out, int out_size) {
    const float* x  = (const float*)d_in[0];   // (4,4096,1024)
    const float* Wg = (const float*)d_in[1];   // (8,1024)
    const float* bg = (const float*)d_in[2];   // (8,)
    const float* We = (const float*)d_in[3];   // (8,1024,1024)
    const float* be = (const float*)d_in[4];   // (8,1024)
    float* out = (float*)d_out;                // (4,4096,1024) f32

    zero_cnt_kernel<<<1, 32>>>();
    gate_kernel<<<NT / 8, 256>>>(x, Wg, bg);   // 8 warps/block = 8 tokens/block

    dim3 grid(NT / BM, FF / BN, NE);           // (256, 16, 8); most x-blocks exit early
    expert_gemm<<<grid, 256>>>(x, We, be);

    combine_kernel<<<(NT * FF / 4) / 256, 256>>>(out);
}

// round 3
// speedup vs baseline: 4.5130x; 4.5130x over previous
#include <cuda_runtime.h>
#include <cuda_bf16.h>
#include <math.h>
#include <stdint.h>

#define NT 16384      // tokens = 4 * 4096
#define DM 1024       // d_model
#define FF 1024       // d_out
#define NE 8          // experts

// GEMM tiling
#define BM 128
#define BN 128
#define BK 32
#define CHUNKS (DM / BK)      // 32

// ---- device scratch (static, allocation-free) ----
__device__ int   g_cnt[NE];
__device__ int   g_list[NE][NT];        // packed: token | (slot<<16)
__device__ float g_w[2][NT];            // gate weight per slot per token
__device__ float g_scr[2][NT][FF];      // per-slot expert outputs (128 MiB)
__device__ __align__(16) __nv_bfloat16 g_xhi[(size_t)NT * DM];
__device__ __align__(16) __nv_bfloat16 g_xlo[(size_t)NT * DM];
__device__ __align__(16) __nv_bfloat16 g_wthi[(size_t)NE * FF * DM];  // [e][n][k]
__device__ __align__(16) __nv_bfloat16 g_wtlo[(size_t)NE * FF * DM];

// ======================= aux kernels =======================
__global__ void zero_cnt_kernel() {
    if (threadIdx.x < NE) g_cnt[threadIdx.x] = 0;
}

// One warp per token: 8 dots of length 1024, warp-reduce, top-2, sigmoid, scatter.
__global__ void gate_kernel(const float* __restrict__ x,
                            const float* __restrict__ Wg,
                            const float* __restrict__ bg) {
    int gwarp = (blockIdx.x * blockDim.x + threadIdx.x) >> 5;
    int lane  = threadIdx.x & 31;
    if (gwarp >= NT) return;

    const float* xr = x + (size_t)gwarp * DM;
    float xv[32];
#pragma unroll
    for (int i = 0; i < 32; i++) xv[i] = xr[lane + 32 * i];

    float logits[NE];
#pragma unroll
    for (int e = 0; e < NE; e++) {
        const float* wg = Wg + e * DM;
        float acc = 0.f;
#pragma unroll
        for (int i = 0; i < 32; i++) acc += xv[i] * wg[lane + 32 * i];
#pragma unroll
        for (int o = 16; o > 0; o >>= 1) acc += __shfl_xor_sync(0xffffffffu, acc, o);
        logits[e] = acc + bg[e];
    }

    if (lane == 0) {
        int b0 = 0; float v0 = logits[0];
#pragma unroll
        for (int e = 1; e < NE; e++) if (logits[e] > v0) { v0 = logits[e]; b0 = e; }
        int b1 = -1; float v1 = -INFINITY;
#pragma unroll
        for (int e = 0; e < NE; e++) if (e != b0 && logits[e] > v1) { v1 = logits[e]; b1 = e; }

        g_w[0][gwarp] = 1.f / (1.f + expf(-v0));
        g_w[1][gwarp] = 1.f / (1.f + expf(-v1));

        int p0 = atomicAdd(&g_cnt[b0], 1);
        g_list[b0][p0] = gwarp;
        int p1 = atomicAdd(&g_cnt[b1], 1);
        g_list[b1][p1] = gwarp | (1 << 16);
    }
}

// x -> (hi, lo) bf16 split, elementwise. 4 floats per thread.
__global__ void split_x_kernel(const float* __restrict__ x) {
    size_t i = ((size_t)blockIdx.x * blockDim.x + threadIdx.x) * 4;
    float4 v = *(const float4*)(x + i);
    __nv_bfloat16 h0 = __float2bfloat16_rn(v.x);
    __nv_bfloat16 h1 = __float2bfloat16_rn(v.y);
    __nv_bfloat16 h2 = __float2bfloat16_rn(v.z);
    __nv_bfloat16 h3 = __float2bfloat16_rn(v.w);
    __nv_bfloat16 l0 = __float2bfloat16_rn(v.x - __bfloat162float(h0));
    __nv_bfloat16 l1 = __float2bfloat16_rn(v.y - __bfloat162float(h1));
    __nv_bfloat16 l2 = __float2bfloat16_rn(v.z - __bfloat162float(h2));
    __nv_bfloat16 l3 = __float2bfloat16_rn(v.w - __bfloat162float(h3));
    *(__nv_bfloat162*)(g_xhi + i)     = __nv_bfloat162(h0, h1);
    *(__nv_bfloat162*)(g_xhi + i + 2) = __nv_bfloat162(h2, h3);
    *(__nv_bfloat162*)(g_xlo + i)     = __nv_bfloat162(l0, l1);
    *(__nv_bfloat162*)(g_xlo + i + 2) = __nv_bfloat162(l2, l3);
}

// We[e][k][n] -> WT_hi/lo[e][n][k] (transpose + split), 32x32 tiles.
__global__ void split_transpose_We(const float* __restrict__ We) {
    __shared__ float tile[32][33];
    int e  = blockIdx.z;
    int k0 = blockIdx.x * 32;
    int n0 = blockIdx.y * 32;
    int tx = threadIdx.x, ty = threadIdx.y;

    const float* src = We + ((size_t)e * DM) * FF;
#pragma unroll
    for (int i = ty; i < 32; i += 8)
        tile[i][tx] = src[(size_t)(k0 + i) * FF + n0 + tx];
    __syncthreads();
#pragma unroll
    for (int i = ty; i < 32; i += 8) {
        float v = tile[tx][i];  // = We[e][k0+tx][n0+i]
        __nv_bfloat16 h = __float2bfloat16_rn(v);
        __nv_bfloat16 l = __float2bfloat16_rn(v - __bfloat162float(h));
        size_t di = ((size_t)e * FF + (n0 + i)) * DM + k0 + tx;
        g_wthi[di] = h;
        g_wtlo[di] = l;
    }
}

// ======================= HMMA expert GEMM =======================
// smem layout (bytes):
//   [0,512)       s_entry (128 int)
//   [512,1024)    s_w     (128 float)
//   [1024, +2*40960) tile stages; per stage 4 tiles (Ahi,Alo,Bhi,Blo),
//   each 128 rows x 80B (64B data + 16B pad)
#define ROWB 80
#define TILEB (128 * ROWB)       // 10240
#define STAGEB (4 * TILEB)       // 40960
#define SM_TILES 1024
#define SM_TOTAL (SM_TILES + 2 * STAGEB)   // 82944

__device__ __forceinline__ uint32_t smem_u32(const void* p) {
    uint32_t a;
    asm("{ .reg .u64 t; cvta.to.shared.u64 t, %1; cvt.u32.u64 %0, t; }" : "=r"(a) : "l"(p));
    return a;
}
#define CP_ASYNC16(dst, src) \
    asm volatile("cp.async.cg.shared.global [%0], [%1], 16;" :: "r"(dst), "l"(src))
#define CP_COMMIT() asm volatile("cp.async.commit_group;")
#define CP_WAIT1()  asm volatile("cp.async.wait_group 1;")
#define CP_WAIT0()  asm volatile("cp.async.wait_group 0;")

__device__ __forceinline__ void ldsm_x4(uint32_t a, uint32_t& r0, uint32_t& r1,
                                        uint32_t& r2, uint32_t& r3) {
    asm volatile("ldmatrix.sync.aligned.m8n8.x4.shared.b16 {%0,%1,%2,%3}, [%4];"
                 : "=r"(r0), "=r"(r1), "=r"(r2), "=r"(r3) : "r"(a));
}
__device__ __forceinline__ void mma16816(float* c, uint32_t a0, uint32_t a1,
                                         uint32_t a2, uint32_t a3,
                                         uint32_t b0, uint32_t b1) {
    asm volatile(
        "mma.sync.aligned.m16n8k16.row.col.f32.bf16.bf16.f32 "
        "{%0,%1,%2,%3}, {%4,%5,%6,%7}, {%8,%9}, {%0,%1,%2,%3};"
        : "+f"(c[0]), "+f"(c[1]), "+f"(c[2]), "+f"(c[3])
        : "r"(a0), "r"(a1), "r"(a2), "r"(a3), "r"(b0), "r"(b1));
}

__global__ void __launch_bounds__(256) expert_gemm_tc(const float* __restrict__ be) {
    extern __shared__ char smem[];
    int e   = blockIdx.z;
    int cnt = g_cnt[e];
    int m0  = blockIdx.x * BM;
    if (m0 >= cnt) return;
    int n0  = blockIdx.y * BN;

    int tid  = threadIdx.x;
    int wid  = tid >> 5;
    int lane = tid & 31;

    int*   s_entry = (int*)smem;
    float* s_w     = (float*)(smem + 512);

    // routing metadata for this row-block
    if (tid < BM) {
        int mi = m0 + tid;
        int entry = (mi < cnt) ? g_list[e][mi] : 0;
        s_entry[tid] = entry;
        s_w[tid]     = g_w[entry >> 16][entry & 0xFFFF];
    }
    __syncthreads();

    // ---- per-thread cp.async granule mapping (8 granules of 16B each) ----
    // granule id = g*256 + tid; tile = id/512; row = (id%512)/4; q = id%4
    const char* gsrc[8];
    uint32_t    gdst[8];
    uint32_t sb = smem_u32(smem);
#pragma unroll
    for (int g = 0; g < 8; g++) {
        int id   = g * 256 + tid;
        int tile = id >> 9;
        int rem  = id & 511;
        int row  = rem >> 2;
        int q    = rem & 3;
        const __nv_bfloat16* base;
        if (tile < 2) {
            int tok = s_entry[row] & 0xFFFF;
            base = (tile == 0 ? g_xhi : g_xlo) + (size_t)tok * DM;
        } else {
            base = (tile == 2 ? g_wthi : g_wtlo) + ((size_t)e * FF + n0 + row) * DM;
        }
        gsrc[g] = (const char*)base + q * 16;
        gdst[g] = sb + SM_TILES + tile * TILEB + row * ROWB + q * 16;
    }

    // ---- ldmatrix per-lane offsets ----
    // A x4 (16x16): r = lane%16, c = lane/16
    uint32_t a_lane = (uint32_t)((lane & 15) * ROWB + (lane >> 4) * 16);
    // B x4 (two 8-row n-tiles x k16): r = lane&7, h=(lane>>3)&1, u=(lane>>4)&1
    uint32_t b_lane = (uint32_t)(((lane >> 4) * 8 + (lane & 7)) * ROWB + ((lane >> 3) & 1) * 16);

    int wm = wid & 1;         // 2 warps in M
    int wn = wid >> 1;        // 4 warps in N
    uint32_t a_warp = a_lane + (uint32_t)(wm * 64) * ROWB;
    uint32_t b_warp = b_lane + (uint32_t)(wn * 32) * ROWB;

    float acc[4][4][4];
#pragma unroll
    for (int i = 0; i < 4; i++)
#pragma unroll
        for (int j = 0; j < 4; j++)
#pragma unroll
            for (int k = 0; k < 4; k++) acc[i][j][k] = 0.f;

    // ---- prefetch chunk 0 ----
    {
#pragma unroll
        for (int g = 0; g < 8; g++) CP_ASYNC16(gdst[g], gsrc[g]);
        CP_COMMIT();
    }

    for (int c = 0; c < CHUNKS; ++c) {
        int st = c & 1;
        if (c + 1 < CHUNKS) {
            size_t koff = (size_t)(c + 1) * BK * 2;   // bytes into k
            uint32_t soff = ((c + 1) & 1) * STAGEB;
#pragma unroll
            for (int g = 0; g < 8; g++) CP_ASYNC16(gdst[g] + soff, gsrc[g] + koff);
            CP_COMMIT();
            CP_WAIT1();
        } else {
            CP_WAIT0();
        }
        __syncthreads();

        uint32_t stage = sb + SM_TILES + st * STAGEB;
        uint32_t Ahi = stage + a_warp;
        uint32_t Alo = Ahi + TILEB;
        uint32_t Bhi = stage + 2 * TILEB + b_warp;
        uint32_t Blo = Bhi + TILEB;

        // 3 passes: (Ahi,Bhi), (Ahi,Blo), (Alo,Bhi)
#pragma unroll
        for (int pass = 0; pass < 3; pass++) {
            uint32_t Ab = (pass == 2) ? Alo : Ahi;
            uint32_t Bb = (pass == 1) ? Blo : Bhi;
#pragma unroll
            for (int s = 0; s < 2; s++) {
                uint32_t kb = (uint32_t)(s * 32);   // 16 bf16 = 32 bytes
                uint32_t a[4][4], b[2][4];
#pragma unroll
                for (int mt = 0; mt < 4; mt++)
                    ldsm_x4(Ab + (uint32_t)(mt * 16) * ROWB + kb,
                            a[mt][0], a[mt][1], a[mt][2], a[mt][3]);
#pragma unroll
                for (int nt2 = 0; nt2 < 2; nt2++)
                    ldsm_x4(Bb + (uint32_t)(nt2 * 16) * ROWB + kb,
                            b[nt2][0], b[nt2][1], b[nt2][2], b[nt2][3]);
#pragma unroll
                for (int mt = 0; mt < 4; mt++) {
#pragma unroll
                    for (int nt = 0; nt < 4; nt++)
                        mma16816(acc[mt][nt],
                                 a[mt][0], a[mt][1], a[mt][2], a[mt][3],
                                 b[nt >> 1][(nt & 1) * 2], b[nt >> 1][(nt & 1) * 2 + 1]);
                }
            }
        }
        __syncthreads();
    }

    // ---- epilogue ----
    int qrow = lane >> 2;          // 0..7
    int qcol = (lane & 3) * 2;     // 0,2,4,6
    float2 bias2[4];
#pragma unroll
    for (int nt = 0; nt < 4; nt++) {
        int nc = n0 + wn * 32 + nt * 8 + qcol;
        bias2[nt] = make_float2(be[e * FF + nc], be[e * FF + nc + 1]);
    }
#pragma unroll
    for (int mt = 0; mt < 4; mt++) {
#pragma unroll
        for (int half = 0; half < 2; half++) {
            int mrow = wm * 64 + mt * 16 + half * 8 + qrow;
            if (m0 + mrow < cnt) {
                int entry = s_entry[mrow];
                int tok   = entry & 0xFFFF;
                int slot  = entry >> 16;
                float w   = s_w[mrow];
#pragma unroll
                for (int nt = 0; nt < 4; nt++) {
                    int nc = n0 + wn * 32 + nt * 8 + qcol;
                    float2 o;
                    o.x = (acc[mt][nt][half * 2 + 0] + bias2[nt].x) * w;
                    o.y = (acc[mt][nt][half * 2 + 1] + bias2[nt].y) * w;
                    *(float2*)&g_scr[slot][tok][nc] = o;
                }
            }
        }
    }
}

// out = scr[0] + scr[1]
__global__ void combine_kernel(float* __restrict__ out) {
    size_t j = (size_t)blockIdx.x * blockDim.x + threadIdx.x;
    const float4* a = (const float4*)g_scr[0];
    const float4* b = (const float4*)g_scr[1];
    float4 u = a[j], v = b[j];
    ((float4*)out)[j] = make_float4(u.x + v.x, u.y + v.y, u.z + v.z, u.w + v.w);
}

extern "C" void kernel_launch(void* const* d_in, const int* in_sizes, int n_in,
                              void* d_out, int out_size) {
    const float* x  = (const float*)d_in[0];   // (4,4096,1024)
    const float* Wg = (const float*)d_in[1];   // (8,1024)
    const float* bg = (const float*)d_in[2];   // (8,)
    const float* We = (const float*)d_in[3];   // (8,1024,1024)
    const float* be = (const float*)d_in[4];   // (8,1024)
    float* out = (float*)d_out;                // (4,4096,1024) f32

    zero_cnt_kernel<<<1, 32>>>();
    gate_kernel<<<NT / 8, 256>>>(x, Wg, bg);

    split_x_kernel<<<(NT * DM / 4) / 256, 256>>>(x);
    split_transpose_We<<<dim3(DM / 32, FF / 32, NE), dim3(32, 8)>>>(We);

    cudaFuncSetAttribute(expert_gemm_tc, cudaFuncAttributeMaxDynamicSharedMemorySize, SM_TOTAL);
    expert_gemm_tc<<<dim3(NT / BM, FF / BN, NE), 256, SM_TOTAL>>>(be);

    combine_kernel<<<(NT * FF / 4) / 256, 256>>>(out);
}

// round 4
// speedup vs baseline: 5.5946x; 1.2397x over previous
#include <cuda_runtime.h>
#include <cuda_bf16.h>
#include <math.h>
#include <stdint.h>

#define NT 16384      // tokens = 4 * 4096
#define DM 1024       // d_model
#define FF 1024       // d_out
#define NE 8          // experts

// GEMM tiling
#define BM 128
#define BN 128
#define BK 32
#define CHUNKS (DM / BK)      // 32

// ---- device scratch (static, allocation-free) ----
__device__ int   g_cnt[NE];
__device__ int   g_list[NE][NT];        // packed: token | (slot<<16)
__device__ float g_w[2][NT];            // gate weight per slot per token
__device__ float g_scr[2][NT][FF];      // per-slot expert outputs (128 MiB)
__device__ __align__(16) __nv_bfloat16 g_xhi[(size_t)NT * DM];
__device__ __align__(16) __nv_bfloat16 g_xlo[(size_t)NT * DM];
__device__ __align__(16) __nv_bfloat16 g_wthi[(size_t)NE * FF * DM];  // [e][n][k]
__device__ __align__(16) __nv_bfloat16 g_wtlo[(size_t)NE * FF * DM];

// ======================= aux kernels =======================
__global__ void zero_cnt_kernel() {
    if (threadIdx.x < NE) g_cnt[threadIdx.x] = 0;
}

// One warp per token: 8 dots of length 1024, warp-reduce, top-2, sigmoid, scatter.
// Also emits the bf16 hi/lo split of x (x already in registers here).
__global__ void gate_kernel(const float* __restrict__ x,
                            const float* __restrict__ Wg,
                            const float* __restrict__ bg) {
    int gwarp = (blockIdx.x * blockDim.x + threadIdx.x) >> 5;
    int lane  = threadIdx.x & 31;
    if (gwarp >= NT) return;

    const float* xr = x + (size_t)gwarp * DM;
    float xv[32];
#pragma unroll
    for (int i = 0; i < 32; i++) xv[i] = xr[lane + 32 * i];

    // hi/lo split store (coalesced 2B per lane, stride-1 across lanes)
    __nv_bfloat16* xh = g_xhi + (size_t)gwarp * DM + lane;
    __nv_bfloat16* xl = g_xlo + (size_t)gwarp * DM + lane;
#pragma unroll
    for (int i = 0; i < 32; i++) {
        __nv_bfloat16 h = __float2bfloat16_rn(xv[i]);
        __nv_bfloat16 l = __float2bfloat16_rn(xv[i] - __bfloat162float(h));
        xh[32 * i] = h;
        xl[32 * i] = l;
    }

    float logits[NE];
#pragma unroll
    for (int e = 0; e < NE; e++) {
        const float* wg = Wg + e * DM;
        float acc = 0.f;
#pragma unroll
        for (int i = 0; i < 32; i++) acc += xv[i] * wg[lane + 32 * i];
#pragma unroll
        for (int o = 16; o > 0; o >>= 1) acc += __shfl_xor_sync(0xffffffffu, acc, o);
        logits[e] = acc + bg[e];
    }

    if (lane == 0) {
        int b0 = 0; float v0 = logits[0];
#pragma unroll
        for (int e = 1; e < NE; e++) if (logits[e] > v0) { v0 = logits[e]; b0 = e; }
        int b1 = -1; float v1 = -INFINITY;
#pragma unroll
        for (int e = 0; e < NE; e++) if (e != b0 && logits[e] > v1) { v1 = logits[e]; b1 = e; }

        g_w[0][gwarp] = 1.f / (1.f + expf(-v0));
        g_w[1][gwarp] = 1.f / (1.f + expf(-v1));

        int p0 = atomicAdd(&g_cnt[b0], 1);
        g_list[b0][p0] = gwarp;
        int p1 = atomicAdd(&g_cnt[b1], 1);
        g_list[b1][p1] = gwarp | (1 << 16);
    }
}

// We[e][k][n] -> WT_hi/lo[e][n][k] (transpose + split), 32x32 tiles.
__global__ void split_transpose_We(const float* __restrict__ We) {
    __shared__ float tile[32][33];
    int e  = blockIdx.z;
    int k0 = blockIdx.x * 32;
    int n0 = blockIdx.y * 32;
    int tx = threadIdx.x, ty = threadIdx.y;

    const float* src = We + ((size_t)e * DM) * FF;
#pragma unroll
    for (int i = ty; i < 32; i += 8)
        tile[i][tx] = src[(size_t)(k0 + i) * FF + n0 + tx];
    __syncthreads();
#pragma unroll
    for (int i = ty; i < 32; i += 8) {
        float v = tile[tx][i];  // = We[e][k0+tx][n0+i]
        __nv_bfloat16 h = __float2bfloat16_rn(v);
        __nv_bfloat16 l = __float2bfloat16_rn(v - __bfloat162float(h));
        size_t di = ((size_t)e * FF + (n0 + i)) * DM + k0 + tx;
        g_wthi[di] = h;
        g_wtlo[di] = l;
    }
}

// ======================= HMMA expert GEMM =======================
// smem layout (bytes):
//   [0,512)       s_entry (128 int)
//   [512,1024)    s_w     (128 float)
//   [1024, +2*40960) tile stages; per stage 4 tiles (Ahi,Alo,Bhi,Blo),
//   each 128 rows x 80B (64B data + 16B pad)
#define ROWB 80
#define TILEB (128 * ROWB)       // 10240
#define STAGEB (4 * TILEB)       // 40960
#define SM_TILES 1024
#define SM_TOTAL (SM_TILES + 2 * STAGEB)   // 82944

__device__ __forceinline__ uint32_t smem_u32(const void* p) {
    uint32_t a;
    asm("{ .reg .u64 t; cvta.to.shared.u64 t, %1; cvt.u32.u64 %0, t; }" : "=r"(a) : "l"(p));
    return a;
}
#define CP_ASYNC16(dst, src) \
    asm volatile("cp.async.cg.shared.global [%0], [%1], 16;" :: "r"(dst), "l"(src))
#define CP_COMMIT() asm volatile("cp.async.commit_group;")
#define CP_WAIT1()  asm volatile("cp.async.wait_group 1;")
#define CP_WAIT0()  asm volatile("cp.async.wait_group 0;")

__device__ __forceinline__ void ldsm_x4(uint32_t a, uint32_t& r0, uint32_t& r1,
                                        uint32_t& r2, uint32_t& r3) {
    asm volatile("ldmatrix.sync.aligned.m8n8.x4.shared.b16 {%0,%1,%2,%3}, [%4];"
                 : "=r"(r0), "=r"(r1), "=r"(r2), "=r"(r3) : "r"(a));
}
__device__ __forceinline__ void mma16816(float* c, uint32_t a0, uint32_t a1,
                                         uint32_t a2, uint32_t a3,
                                         uint32_t b0, uint32_t b1) {
    asm volatile(
        "mma.sync.aligned.m16n8k16.row.col.f32.bf16.bf16.f32 "
        "{%0,%1,%2,%3}, {%4,%5,%6,%7}, {%8,%9}, {%0,%1,%2,%3};"
        : "+f"(c[0]), "+f"(c[1]), "+f"(c[2]), "+f"(c[3])
        : "r"(a0), "r"(a1), "r"(a2), "r"(a3), "r"(b0), "r"(b1));
}

__global__ void __launch_bounds__(256, 2) expert_gemm_tc(const float* __restrict__ be) {
    extern __shared__ char smem[];
    int e   = blockIdx.z;
    int cnt = g_cnt[e];
    int m0  = blockIdx.x * BM;
    if (m0 >= cnt) return;
    int n0  = blockIdx.y * BN;

    int tid  = threadIdx.x;
    int wid  = tid >> 5;
    int lane = tid & 31;

    int*   s_entry = (int*)smem;
    float* s_w     = (float*)(smem + 512);

    // routing metadata for this row-block
    if (tid < BM) {
        int mi = m0 + tid;
        int entry = (mi < cnt) ? g_list[e][mi] : 0;
        s_entry[tid] = entry;
        s_w[tid]     = g_w[entry >> 16][entry & 0xFFFF];
    }
    __syncthreads();

    // ---- cp.async mapping: thread covers rows r0 and r0+64 of all 4 tiles, 16B quarter q ----
    int r0 = tid >> 2;           // 0..63
    int q  = tid & 3;            // 16B quarter within 64B row
    size_t xoff0 = (size_t)(s_entry[r0] & 0xFFFF) * DM + q * 8;
    size_t xoff1 = (size_t)(s_entry[r0 + 64] & 0xFFFF) * DM + q * 8;
    size_t woff0 = ((size_t)e * FF + n0 + r0) * DM + q * 8;
    size_t woff1 = woff0 + (size_t)64 * DM;

    uint32_t sb = smem_u32(smem);
    uint32_t dA0 = sb + SM_TILES + (uint32_t)(r0 * ROWB + q * 16);
    uint32_t dA1 = dA0 + 64 * ROWB;

    // ---- ldmatrix per-lane offsets ----
    uint32_t a_lane = (uint32_t)((lane & 15) * ROWB + (lane >> 4) * 16);
    uint32_t b_lane = (uint32_t)(((lane >> 4) * 8 + (lane & 7)) * ROWB + ((lane >> 3) & 1) * 16);

    int wm = wid & 1;         // 2 warps in M
    int wn = wid >> 1;        // 4 warps in N
    uint32_t a_warp = a_lane + (uint32_t)(wm * 64) * ROWB;
    uint32_t b_warp = b_lane + (uint32_t)(wn * 32) * ROWB;

    float acc[4][4][4];
#pragma unroll
    for (int i = 0; i < 4; i++)
#pragma unroll
        for (int j = 0; j < 4; j++)
#pragma unroll
            for (int k = 0; k < 4; k++) acc[i][j][k] = 0.f;

#define FILL_STAGE(stoff, koff) do {                                               \
        uint32_t d = (stoff);                                                      \
        CP_ASYNC16(dA0 + d,             (const char*)(g_xhi  + xoff0 + (koff)));   \
        CP_ASYNC16(dA1 + d,             (const char*)(g_xhi  + xoff1 + (koff)));   \
        CP_ASYNC16(dA0 + d + TILEB,     (const char*)(g_xlo  + xoff0 + (koff)));   \
        CP_ASYNC16(dA1 + d + TILEB,     (const char*)(g_xlo  + xoff1 + (koff)));   \
        CP_ASYNC16(dA0 + d + 2 * TILEB, (const char*)(g_wthi + woff0 + (koff)));   \
        CP_ASYNC16(dA1 + d + 2 * TILEB, (const char*)(g_wthi + woff1 + (koff)));   \
        CP_ASYNC16(dA0 + d + 3 * TILEB, (const char*)(g_wtlo + woff0 + (koff)));   \
        CP_ASYNC16(dA1 + d + 3 * TILEB, (const char*)(g_wtlo + woff1 + (koff)));   \
        CP_COMMIT();                                                               \
    } while (0)

    FILL_STAGE(0, 0);

    for (int c = 0; c < CHUNKS; ++c) {
        int st = c & 1;
        if (c + 1 < CHUNKS) {
            FILL_STAGE(((c + 1) & 1) * STAGEB, (size_t)(c + 1) * BK);
            CP_WAIT1();
        } else {
            CP_WAIT0();
        }
        __syncthreads();

        uint32_t stage = sb + SM_TILES + st * STAGEB;
        uint32_t Ahi = stage + a_warp;
        uint32_t Alo = Ahi + TILEB;
        uint32_t Bhi = stage + 2 * TILEB + b_warp;
        uint32_t Blo = Bhi + TILEB;

#pragma unroll
        for (int s = 0; s < 2; s++) {
            uint32_t kb = (uint32_t)(s * 32);   // 16 bf16 = 32 bytes

            // pass 0: Ahi x Bhi  (load Ahi, Bhi once; reuse below)
            uint32_t ah[4][4], bh[2][4];
#pragma unroll
            for (int mt = 0; mt < 4; mt++)
                ldsm_x4(Ahi + (uint32_t)(mt * 16) * ROWB + kb,
                        ah[mt][0], ah[mt][1], ah[mt][2], ah[mt][3]);
#pragma unroll
            for (int n2 = 0; n2 < 2; n2++)
                ldsm_x4(Bhi + (uint32_t)(n2 * 16) * ROWB + kb,
                        bh[n2][0], bh[n2][1], bh[n2][2], bh[n2][3]);
#pragma unroll
            for (int mt = 0; mt < 4; mt++)
#pragma unroll
                for (int nt = 0; nt < 4; nt++)
                    mma16816(acc[mt][nt], ah[mt][0], ah[mt][1], ah[mt][2], ah[mt][3],
                             bh[nt >> 1][(nt & 1) * 2], bh[nt >> 1][(nt & 1) * 2 + 1]);

            // pass 1: Ahi x Blo  (reuse ah)
            {
                uint32_t bl[2][4];
#pragma unroll
                for (int n2 = 0; n2 < 2; n2++)
                    ldsm_x4(Blo + (uint32_t)(n2 * 16) * ROWB + kb,
                            bl[n2][0], bl[n2][1], bl[n2][2], bl[n2][3]);
#pragma unroll
                for (int mt = 0; mt < 4; mt++)
#pragma unroll
                    for (int nt = 0; nt < 4; nt++)
                        mma16816(acc[mt][nt], ah[mt][0], ah[mt][1], ah[mt][2], ah[mt][3],
                                 bl[nt >> 1][(nt & 1) * 2], bl[nt >> 1][(nt & 1) * 2 + 1]);
            }

            // pass 2: Alo x Bhi  (reuse bh; ah dead)
            {
                uint32_t al[4][4];
#pragma unroll
                for (int mt = 0; mt < 4; mt++)
                    ldsm_x4(Alo + (uint32_t)(mt * 16) * ROWB + kb,
                            al[mt][0], al[mt][1], al[mt][2], al[mt][3]);
#pragma unroll
                for (int mt = 0; mt < 4; mt++)
#pragma unroll
                    for (int nt = 0; nt < 4; nt++)
                        mma16816(acc[mt][nt], al[mt][0], al[mt][1], al[mt][2], al[mt][3],
                                 bh[nt >> 1][(nt & 1) * 2], bh[nt >> 1][(nt & 1) * 2 + 1]);
            }
        }
        __syncthreads();
    }

    // ---- epilogue ----
    int qrow = lane >> 2;          // 0..7
    int qcol = (lane & 3) * 2;     // 0,2,4,6
    float2 bias2[4];
#pragma unroll
    for (int nt = 0; nt < 4; nt++) {
        int nc = n0 + wn * 32 + nt * 8 + qcol;
        bias2[nt] = make_float2(be[e * FF + nc], be[e * FF + nc + 1]);
    }
#pragma unroll
    for (int mt = 0; mt < 4; mt++) {
#pragma unroll
        for (int half = 0; half < 2; half++) {
            int mrow = wm * 64 + mt * 16 + half * 8 + qrow;
            if (m0 + mrow < cnt) {
                int entry = s_entry[mrow];
                int tok   = entry & 0xFFFF;
                int slot  = entry >> 16;
                float w   = s_w[mrow];
#pragma unroll
                for (int nt = 0; nt < 4; nt++) {
                    int nc = n0 + wn * 32 + nt * 8 + qcol;
                    float2 o;
                    o.x = (acc[mt][nt][half * 2 + 0] + bias2[nt].x) * w;
                    o.y = (acc[mt][nt][half * 2 + 1] + bias2[nt].y) * w;
                    *(float2*)&g_scr[slot][tok][nc] = o;
                }
            }
        }
    }
}

// out = scr[0] + scr[1]
__global__ void combine_kernel(float* __restrict__ out) {
    size_t j = (size_t)blockIdx.x * blockDim.x + threadIdx.x;
    const float4* a = (const float4*)g_scr[0];
    const float4* b = (const float4*)g_scr[1];
    float4 u = a[j], v = b[j];
    ((float4*)out)[j] = make_float4(u.x + v.x, u.y + v.y, u.z + v.z, u.w + v.w);
}

extern "C" void kernel_launch(void* const* d_in, const int* in_sizes, int n_in,
                              void* d_out, int out_size) {
    const float* x  = (const float*)d_in[0];   // (4,4096,1024)
    const float* Wg = (const float*)d_in[1];   // (8,1024)
    const float* bg = (const float*)d_in[2];   // (8,)
    const float* We = (const float*)d_in[3];   // (8,1024,1024)
    const float* be = (const float*)d_in[4];   // (8,1024)
    float* out = (float*)d_out;                // (4,4096,1024) f32

    zero_cnt_kernel<<<1, 32>>>();
    gate_kernel<<<NT / 8, 256>>>(x, Wg, bg);

    split_transpose_We<<<dim3(DM / 32, FF / 32, NE), dim3(32, 8)>>>(We);

    cudaFuncSetAttribute(expert_gemm_tc, cudaFuncAttributeMaxDynamicSharedMemorySize, SM_TOTAL);
    expert_gemm_tc<<<dim3(NT / BM, FF / BN, NE), 256, SM_TOTAL>>>(be);

    combine_kernel<<<(NT * FF / 4) / 256, 256>>>(out);
}

// round 5
// speedup vs baseline: 7.5499x; 1.3495x over previous
#include <cuda_runtime.h>
#include <cuda_fp16.h>
#include <math.h>
#include <stdint.h>

#define NT 16384      // tokens = 4 * 4096
#define DM 1024       // d_model
#define FF 1024       // d_out
#define NE 8          // experts

// GEMM tiling
#define BM 128
#define BN 128
#define BK 32
#define CHUNKS (DM / BK)      // 32

// ---- device scratch (static, allocation-free) ----
__device__ int   g_cnt[NE];
__device__ int   g_list[NE][NT];        // packed: token | (slot<<16)
__device__ float g_w[2][NT];            // gate weight per slot per token
__device__ float g_scr[2][NT][FF];      // per-slot expert outputs (128 MiB)
__device__ __align__(16) __half g_xhi[(size_t)NT * DM];
__device__ __align__(16) __half g_xlo[(size_t)NT * DM];
__device__ __align__(16) __half g_wthi[(size_t)NE * FF * DM];  // [e][n][k], fp16

// ======================= aux kernels =======================
__global__ void zero_cnt_kernel() {
    if (threadIdx.x < NE) g_cnt[threadIdx.x] = 0;
}

// One warp per token: 8 dots of length 1024, warp-reduce, top-2, sigmoid, scatter.
// Also emits the fp16 hi/lo split of x (x already in registers here).
__global__ void gate_kernel(const float* __restrict__ x,
                            const float* __restrict__ Wg,
                            const float* __restrict__ bg) {
    int gwarp = (blockIdx.x * blockDim.x + threadIdx.x) >> 5;
    int lane  = threadIdx.x & 31;
    if (gwarp >= NT) return;

    const float* xr = x + (size_t)gwarp * DM;
    float xv[32];
#pragma unroll
    for (int i = 0; i < 32; i++) xv[i] = xr[lane + 32 * i];

    // hi/lo fp16 split store (coalesced 2B per lane)
    __half* xh = g_xhi + (size_t)gwarp * DM + lane;
    __half* xl = g_xlo + (size_t)gwarp * DM + lane;
#pragma unroll
    for (int i = 0; i < 32; i++) {
        __half h = __float2half_rn(xv[i]);
        __half l = __float2half_rn(xv[i] - __half2float(h));
        xh[32 * i] = h;
        xl[32 * i] = l;
    }

    float logits[NE];
#pragma unroll
    for (int e = 0; e < NE; e++) {
        const float* wg = Wg + e * DM;
        float acc = 0.f;
#pragma unroll
        for (int i = 0; i < 32; i++) acc += xv[i] * wg[lane + 32 * i];
#pragma unroll
        for (int o = 16; o > 0; o >>= 1) acc += __shfl_xor_sync(0xffffffffu, acc, o);
        logits[e] = acc + bg[e];
    }

    if (lane == 0) {
        int b0 = 0; float v0 = logits[0];
#pragma unroll
        for (int e = 1; e < NE; e++) if (logits[e] > v0) { v0 = logits[e]; b0 = e; }
        int b1 = -1; float v1 = -INFINITY;
#pragma unroll
        for (int e = 0; e < NE; e++) if (e != b0 && logits[e] > v1) { v1 = logits[e]; b1 = e; }

        g_w[0][gwarp] = 1.f / (1.f + expf(-v0));
        g_w[1][gwarp] = 1.f / (1.f + expf(-v1));

        int p0 = atomicAdd(&g_cnt[b0], 1);
        g_list[b0][p0] = gwarp;
        int p1 = atomicAdd(&g_cnt[b1], 1);
        g_list[b1][p1] = gwarp | (1 << 16);
    }
}

// We[e][k][n] -> WT_hi[e][n][k] (transpose, fp16), 32x32 tiles.
__global__ void split_transpose_We(const float* __restrict__ We) {
    __shared__ float tile[32][33];
    int e  = blockIdx.z;
    int k0 = blockIdx.x * 32;
    int n0 = blockIdx.y * 32;
    int tx = threadIdx.x, ty = threadIdx.y;

    const float* src = We + ((size_t)e * DM) * FF;
#pragma unroll
    for (int i = ty; i < 32; i += 8)
        tile[i][tx] = src[(size_t)(k0 + i) * FF + n0 + tx];
    __syncthreads();
#pragma unroll
    for (int i = ty; i < 32; i += 8) {
        float v = tile[tx][i];  // = We[e][k0+tx][n0+i]
        size_t di = ((size_t)e * FF + (n0 + i)) * DM + k0 + tx;
        g_wthi[di] = __float2half_rn(v);
    }
}

// ======================= HMMA expert GEMM =======================
// smem layout (bytes):
//   [0,512)    s_entry (128 int)
//   [512,1024) s_w     (128 float)
//   [1024, +3*30720) 3 stages; per stage 3 tiles (Ahi,Alo,Bhi),
//   each 128 rows x 80B (64B data + 16B pad)
#define ROWB 80
#define TILEB (128 * ROWB)       // 10240
#define STAGEB (3 * TILEB)       // 30720
#define SM_TILES 1024
#define SM_TOTAL (SM_TILES + 3 * STAGEB)   // 93184

__device__ __forceinline__ uint32_t smem_u32(const void* p) {
    uint32_t a;
    asm("{ .reg .u64 t; cvta.to.shared.u64 t, %1; cvt.u32.u64 %0, t; }" : "=r"(a) : "l"(p));
    return a;
}
#define CP_ASYNC16(dst, src) \
    asm volatile("cp.async.cg.shared.global [%0], [%1], 16;" :: "r"(dst), "l"(src))
#define CP_COMMIT() asm volatile("cp.async.commit_group;")
#define CP_WAIT1()  asm volatile("cp.async.wait_group 1;")
#define CP_WAIT0()  asm volatile("cp.async.wait_group 0;")

__device__ __forceinline__ void ldsm_x4(uint32_t a, uint32_t& r0, uint32_t& r1,
                                        uint32_t& r2, uint32_t& r3) {
    asm volatile("ldmatrix.sync.aligned.m8n8.x4.shared.b16 {%0,%1,%2,%3}, [%4];"
                 : "=r"(r0), "=r"(r1), "=r"(r2), "=r"(r3) : "r"(a));
}
__device__ __forceinline__ void mma16816(float* c, uint32_t a0, uint32_t a1,
                                         uint32_t a2, uint32_t a3,
                                         uint32_t b0, uint32_t b1) {
    asm volatile(
        "mma.sync.aligned.m16n8k16.row.col.f32.f16.f16.f32 "
        "{%0,%1,%2,%3}, {%4,%5,%6,%7}, {%8,%9}, {%0,%1,%2,%3};"
        : "+f"(c[0]), "+f"(c[1]), "+f"(c[2]), "+f"(c[3])
        : "r"(a0), "r"(a1), "r"(a2), "r"(a3), "r"(b0), "r"(b1));
}

__global__ void __launch_bounds__(256, 2) expert_gemm_tc(const float* __restrict__ be) {
    extern __shared__ char smem[];
    int e   = blockIdx.z;
    int cnt = g_cnt[e];
    int m0  = blockIdx.x * BM;
    if (m0 >= cnt) return;
    int n0  = blockIdx.y * BN;

    int tid  = threadIdx.x;
    int wid  = tid >> 5;
    int lane = tid & 31;

    int*   s_entry = (int*)smem;
    float* s_w     = (float*)(smem + 512);

    // routing metadata for this row-block
    if (tid < BM) {
        int mi = m0 + tid;
        int entry = (mi < cnt) ? g_list[e][mi] : 0;
        s_entry[tid] = entry;
        s_w[tid]     = g_w[entry >> 16][entry & 0xFFFF];
    }
    __syncthreads();

    // ---- cp.async mapping: thread covers rows r0 and r0+64 of all 3 tiles, 16B quarter q ----
    int r0 = tid >> 2;           // 0..63
    int q  = tid & 3;            // 16B quarter within 64B row
    size_t xoff0 = (size_t)(s_entry[r0] & 0xFFFF) * DM + q * 8;
    size_t xoff1 = (size_t)(s_entry[r0 + 64] & 0xFFFF) * DM + q * 8;
    size_t woff0 = ((size_t)e * FF + n0 + r0) * DM + q * 8;
    size_t woff1 = woff0 + (size_t)64 * DM;

    uint32_t sb = smem_u32(smem);
    uint32_t dA0 = sb + SM_TILES + (uint32_t)(r0 * ROWB + q * 16);
    uint32_t dA1 = dA0 + 64 * ROWB;

    // ---- ldmatrix per-lane offsets ----
    uint32_t a_lane = (uint32_t)((lane & 15) * ROWB + (lane >> 4) * 16);
    uint32_t b_lane = (uint32_t)(((lane >> 4) * 8 + (lane & 7)) * ROWB + ((lane >> 3) & 1) * 16);

    int wm = wid & 1;         // 2 warps in M
    int wn = wid >> 1;        // 4 warps in N
    uint32_t a_warp = a_lane + (uint32_t)(wm * 64) * ROWB;
    uint32_t b_warp = b_lane + (uint32_t)(wn * 32) * ROWB;

    float acc[4][4][4];
#pragma unroll
    for (int i = 0; i < 4; i++)
#pragma unroll
        for (int j = 0; j < 4; j++)
#pragma unroll
            for (int k = 0; k < 4; k++) acc[i][j][k] = 0.f;

#define FILL_STAGE(stoff, koff) do {                                               \
        uint32_t d = (stoff);                                                      \
        CP_ASYNC16(dA0 + d,             (const char*)(g_xhi  + xoff0 + (koff)));   \
        CP_ASYNC16(dA1 + d,             (const char*)(g_xhi  + xoff1 + (koff)));   \
        CP_ASYNC16(dA0 + d + TILEB,     (const char*)(g_xlo  + xoff0 + (koff)));   \
        CP_ASYNC16(dA1 + d + TILEB,     (const char*)(g_xlo  + xoff1 + (koff)));   \
        CP_ASYNC16(dA0 + d + 2 * TILEB, (const char*)(g_wthi + woff0 + (koff)));   \
        CP_ASYNC16(dA1 + d + 2 * TILEB, (const char*)(g_wthi + woff1 + (koff)));   \
        CP_COMMIT();                                                               \
    } while (0)

    // prologue: stages 0 and 1 in flight
    FILL_STAGE(0, 0);
    FILL_STAGE(STAGEB, (size_t)BK);

    int st = 0;   // stage being computed (c % 3)
    int fs = 2;   // stage to fill ((c+2) % 3)
    for (int c = 0; c < CHUNKS; ++c) {
        if (c + 1 < CHUNKS) { CP_WAIT1(); } else { CP_WAIT0(); }
        __syncthreads();                       // all warps done reading stage fs (iter c-1)
        if (c + 2 < CHUNKS)
            FILL_STAGE((uint32_t)fs * STAGEB, (size_t)(c + 2) * BK);

        uint32_t stage = sb + SM_TILES + (uint32_t)st * STAGEB;
        uint32_t Ahi = stage + a_warp;
        uint32_t Alo = Ahi + TILEB;
        uint32_t Bhi = stage + 2 * TILEB + b_warp;

#pragma unroll
        for (int s = 0; s < 2; s++) {
            uint32_t kb = (uint32_t)(s * 32);   // 16 fp16 = 32 bytes

            // pass 0: Ahi x Bhi
            uint32_t ah[4][4], bh[2][4];
#pragma unroll
            for (int mt = 0; mt < 4; mt++)
                ldsm_x4(Ahi + (uint32_t)(mt * 16) * ROWB + kb,
                        ah[mt][0], ah[mt][1], ah[mt][2], ah[mt][3]);
#pragma unroll
            for (int n2 = 0; n2 < 2; n2++)
                ldsm_x4(Bhi + (uint32_t)(n2 * 16) * ROWB + kb,
                        bh[n2][0], bh[n2][1], bh[n2][2], bh[n2][3]);
#pragma unroll
            for (int mt = 0; mt < 4; mt++)
#pragma unroll
                for (int nt = 0; nt < 4; nt++)
                    mma16816(acc[mt][nt], ah[mt][0], ah[mt][1], ah[mt][2], ah[mt][3],
                             bh[nt >> 1][(nt & 1) * 2], bh[nt >> 1][(nt & 1) * 2 + 1]);

            // pass 1: Alo x Bhi  (reuse bh; ah dead)
            {
                uint32_t al[4][4];
#pragma unroll
                for (int mt = 0; mt < 4; mt++)
                    ldsm_x4(Alo + (uint32_t)(mt * 16) * ROWB + kb,
                            al[mt][0], al[mt][1], al[mt][2], al[mt][3]);
#pragma unroll
                for (int mt = 0; mt < 4; mt++)
#pragma unroll
                    for (int nt = 0; nt < 4; nt++)
                        mma16816(acc[mt][nt], al[mt][0], al[mt][1], al[mt][2], al[mt][3],
                                 bh[nt >> 1][(nt & 1) * 2], bh[nt >> 1][(nt & 1) * 2 + 1]);
            }
        }
        st = (st == 2) ? 0 : st + 1;
        fs = (fs == 2) ? 0 : fs + 1;
    }

    // ---- epilogue ----
    int qrow = lane >> 2;          // 0..7
    int qcol = (lane & 3) * 2;     // 0,2,4,6
    float2 bias2[4];
#pragma unroll
    for (int nt = 0; nt < 4; nt++) {
        int nc = n0 + wn * 32 + nt * 8 + qcol;
        bias2[nt] = make_float2(be[e * FF + nc], be[e * FF + nc + 1]);
    }
#pragma unroll
    for (int mt = 0; mt < 4; mt++) {
#pragma unroll
        for (int half = 0; half < 2; half++) {
            int mrow = wm * 64 + mt * 16 + half * 8 + qrow;
            if (m0 + mrow < cnt) {
                int entry = s_entry[mrow];
                int tok   = entry & 0xFFFF;
                int slot  = entry >> 16;
                float w   = s_w[mrow];
#pragma unroll
                for (int nt = 0; nt < 4; nt++) {
                    int nc = n0 + wn * 32 + nt * 8 + qcol;
                    float2 o;
                    o.x = (acc[mt][nt][half * 2 + 0] + bias2[nt].x) * w;
                    o.y = (acc[mt][nt][half * 2 + 1] + bias2[nt].y) * w;
                    *(float2*)&g_scr[slot][tok][nc] = o;
                }
            }
        }
    }
}

// out = scr[0] + scr[1]
__global__ void combine_kernel(float* __restrict__ out) {
    size_t j = (size_t)blockIdx.x * blockDim.x + threadIdx.x;
    const float4* a = (const float4*)g_scr[0];
    const float4* b = (const float4*)g_scr[1];
    float4 u = a[j], v = b[j];
    ((float4*)out)[j] = make_float4(u.x + v.x, u.y + v.y, u.z + v.z, u.w + v.w);
}

extern "C" void kernel_launch(void* const* d_in, const int* in_sizes, int n_in,
                              void* d_out, int out_size) {
    const float* x  = (const float*)d_in[0];   // (4,4096,1024)
    const float* Wg = (const float*)d_in[1];   // (8,1024)
    const float* bg = (const float*)d_in[2];   // (8,)
    const float* We = (const float*)d_in[3];   // (8,1024,1024)
    const float* be = (const float*)d_in[4];   // (8,1024)
    float* out = (float*)d_out;                // (4,4096,1024) f32

    zero_cnt_kernel<<<1, 32>>>();
    gate_kernel<<<NT / 8, 256>>>(x, Wg, bg);

    split_transpose_We<<<dim3(DM / 32, FF / 32, NE), dim3(32, 8)>>>(We);

    cudaFuncSetAttribute(expert_gemm_tc, cudaFuncAttributeMaxDynamicSharedMemorySize, SM_TOTAL);
    expert_gemm_tc<<<dim3(NT / BM, FF / BN, NE), 256, SM_TOTAL>>>(be);

    combine_kernel<<<(NT * FF / 4) / 256, 256>>>(out);
}

// round 6
// speedup vs baseline: 9.0140x; 1.1939x over previous
#include <cuda_runtime.h>
#include <cuda_fp16.h>
#include <math.h>
#include <stdint.h>

#define NT 16384      // tokens = 4 * 4096
#define DM 1024       // d_model
#define FF 1024       // d_out
#define NE 8          // experts

// GEMM tiling
#define BM 128
#define BN 128
#define BK 64
#define CHUNKS (DM / BK)      // 16

// ---- device scratch (static, allocation-free) ----
__device__ int   g_cnt[NE];
__device__ int   g_list[NE][NT];        // packed: token | (slot<<16)
__device__ float g_w[2][NT];            // gate weight per slot per token
__device__ float g_scr[2][NT][FF];      // per-slot expert outputs (128 MiB)
__device__ __align__(16) __half g_xh[(size_t)NT * DM];          // fp16 x
__device__ __align__(16) __half g_wt[(size_t)NE * FF * DM];     // [e][n][k], fp16

// ======================= aux kernels =======================
__global__ void zero_cnt_kernel() {
    if (threadIdx.x < NE) g_cnt[threadIdx.x] = 0;
}

// One warp per token: 8 dots of length 1024, warp-reduce, top-2, sigmoid, scatter.
// Also emits fp16 x (x already in registers here).
__global__ void gate_kernel(const float* __restrict__ x,
                            const float* __restrict__ Wg,
                            const float* __restrict__ bg) {
    int gwarp = (blockIdx.x * blockDim.x + threadIdx.x) >> 5;
    int lane  = threadIdx.x & 31;
    if (gwarp >= NT) return;

    const float* xr = x + (size_t)gwarp * DM;
    float xv[32];
#pragma unroll
    for (int i = 0; i < 32; i++) xv[i] = xr[lane + 32 * i];

    __half* xh = g_xh + (size_t)gwarp * DM + lane;
#pragma unroll
    for (int i = 0; i < 32; i++) xh[32 * i] = __float2half_rn(xv[i]);

    float logits[NE];
#pragma unroll
    for (int e = 0; e < NE; e++) {
        const float* wg = Wg + e * DM;
        float acc = 0.f;
#pragma unroll
        for (int i = 0; i < 32; i++) acc += xv[i] * wg[lane + 32 * i];
#pragma unroll
        for (int o = 16; o > 0; o >>= 1) acc += __shfl_xor_sync(0xffffffffu, acc, o);
        logits[e] = acc + bg[e];
    }

    if (lane == 0) {
        int b0 = 0; float v0 = logits[0];
#pragma unroll
        for (int e = 1; e < NE; e++) if (logits[e] > v0) { v0 = logits[e]; b0 = e; }
        int b1 = -1; float v1 = -INFINITY;
#pragma unroll
        for (int e = 0; e < NE; e++) if (e != b0 && logits[e] > v1) { v1 = logits[e]; b1 = e; }

        g_w[0][gwarp] = 1.f / (1.f + expf(-v0));
        g_w[1][gwarp] = 1.f / (1.f + expf(-v1));

        int p0 = atomicAdd(&g_cnt[b0], 1);
        g_list[b0][p0] = gwarp;
        int p1 = atomicAdd(&g_cnt[b1], 1);
        g_list[b1][p1] = gwarp | (1 << 16);
    }
}

// We[e][k][n] -> WT[e][n][k] (transpose, fp16), 32x32 tiles.
__global__ void split_transpose_We(const float* __restrict__ We) {
    __shared__ float tile[32][33];
    int e  = blockIdx.z;
    int k0 = blockIdx.x * 32;
    int n0 = blockIdx.y * 32;
    int tx = threadIdx.x, ty = threadIdx.y;

    const float* src = We + ((size_t)e * DM) * FF;
#pragma unroll
    for (int i = ty; i < 32; i += 8)
        tile[i][tx] = src[(size_t)(k0 + i) * FF + n0 + tx];
    __syncthreads();
#pragma unroll
    for (int i = ty; i < 32; i += 8) {
        float v = tile[tx][i];  // = We[e][k0+tx][n0+i]
        size_t di = ((size_t)e * FF + (n0 + i)) * DM + k0 + tx;
        g_wt[di] = __float2half_rn(v);
    }
}

// ======================= HMMA expert GEMM =======================
// smem layout (bytes):
//   [0,512)    s_entry (128 int)
//   [512,1024) s_w     (128 float)
//   [1024, +2*36864) 2 stages; per stage A tile then B tile,
//   each 128 rows x 144B (128B data + 16B pad)
#define ROWB 144
#define TILEB (128 * ROWB)       // 18432
#define STAGEB (2 * TILEB)       // 36864
#define SM_TILES 1024
#define SM_TOTAL (SM_TILES + 2 * STAGEB)   // 74752

__device__ __forceinline__ uint32_t smem_u32(const void* p) {
    uint32_t a;
    asm("{ .reg .u64 t; cvta.to.shared.u64 t, %1; cvt.u32.u64 %0, t; }" : "=r"(a) : "l"(p));
    return a;
}
#define CP_ASYNC16(dst, src) \
    asm volatile("cp.async.cg.shared.global [%0], [%1], 16;" :: "r"(dst), "l"(src))
#define CP_COMMIT() asm volatile("cp.async.commit_group;")
#define CP_WAIT1()  asm volatile("cp.async.wait_group 1;")
#define CP_WAIT0()  asm volatile("cp.async.wait_group 0;")

__device__ __forceinline__ void ldsm_x4(uint32_t a, uint32_t& r0, uint32_t& r1,
                                        uint32_t& r2, uint32_t& r3) {
    asm volatile("ldmatrix.sync.aligned.m8n8.x4.shared.b16 {%0,%1,%2,%3}, [%4];"
                 : "=r"(r0), "=r"(r1), "=r"(r2), "=r"(r3) : "r"(a));
}
__device__ __forceinline__ void mma16816(float* c, uint32_t a0, uint32_t a1,
                                         uint32_t a2, uint32_t a3,
                                         uint32_t b0, uint32_t b1) {
    asm volatile(
        "mma.sync.aligned.m16n8k16.row.col.f32.f16.f16.f32 "
        "{%0,%1,%2,%3}, {%4,%5,%6,%7}, {%8,%9}, {%0,%1,%2,%3};"
        : "+f"(c[0]), "+f"(c[1]), "+f"(c[2]), "+f"(c[3])
        : "r"(a0), "r"(a1), "r"(a2), "r"(a3), "r"(b0), "r"(b1));
}

__global__ void __launch_bounds__(256, 2) expert_gemm_tc(const float* __restrict__ be) {
    extern __shared__ char smem[];
    int e   = blockIdx.z;
    int cnt = g_cnt[e];
    int m0  = blockIdx.x * BM;
    if (m0 >= cnt) return;
    int n0  = blockIdx.y * BN;

    int tid  = threadIdx.x;
    int wid  = tid >> 5;
    int lane = tid & 31;

    int*   s_entry = (int*)smem;
    float* s_w     = (float*)(smem + 512);

    // routing metadata for this row-block
    if (tid < BM) {
        int mi = m0 + tid;
        int entry = (mi < cnt) ? g_list[e][mi] : 0;
        s_entry[tid] = entry;
        s_w[tid]     = g_w[entry >> 16][entry & 0xFFFF];
    }
    __syncthreads();

    // ---- cp.async mapping: thread t covers row r = t>>1, half h = t&1 of both tiles;
    //      each fill is 4 x 16B (64B half-row) per tile, 8 cp.async total ----
    int r = tid >> 1;            // 0..127
    int h = tid & 1;             // half-row (32 fp16 = 64B)
    size_t xbase = (size_t)(s_entry[r] & 0xFFFF) * DM + h * 32;
    size_t wbase = ((size_t)e * FF + n0 + r) * DM + h * 32;

    uint32_t sb  = smem_u32(smem);
    uint32_t dst = sb + SM_TILES + (uint32_t)(r * ROWB + h * 64);

#define FILL_STAGE(stoff, kelem) do {                                              \
        uint32_t d = (stoff);                                                      \
        const char* sa = (const char*)(g_xh + xbase + (kelem));                    \
        const char* sw = (const char*)(g_wt + wbase + (kelem));                    \
        CP_ASYNC16(dst + d,              sa);                                      \
        CP_ASYNC16(dst + d + 16,         sa + 16);                                 \
        CP_ASYNC16(dst + d + 32,         sa + 32);                                 \
        CP_ASYNC16(dst + d + 48,         sa + 48);                                 \
        CP_ASYNC16(dst + d + TILEB,      sw);                                      \
        CP_ASYNC16(dst + d + TILEB + 16, sw + 16);                                 \
        CP_ASYNC16(dst + d + TILEB + 32, sw + 32);                                 \
        CP_ASYNC16(dst + d + TILEB + 48, sw + 48);                                 \
        CP_COMMIT();                                                               \
    } while (0)

    // ---- ldmatrix per-lane offsets ----
    uint32_t a_lane = (uint32_t)((lane & 15) * ROWB + (lane >> 4) * 16);
    uint32_t b_lane = (uint32_t)(((lane >> 4) * 8 + (lane & 7)) * ROWB + ((lane >> 3) & 1) * 16);

    int wm = wid & 1;         // 2 warps in M
    int wn = wid >> 1;        // 4 warps in N
    uint32_t a_warp = a_lane + (uint32_t)(wm * 64) * ROWB;
    uint32_t b_warp = b_lane + (uint32_t)(wn * 32) * ROWB;

    float acc[4][4][4];
#pragma unroll
    for (int i = 0; i < 4; i++)
#pragma unroll
        for (int j = 0; j < 4; j++)
#pragma unroll
            for (int k = 0; k < 4; k++) acc[i][j][k] = 0.f;

    FILL_STAGE(0, 0);

    for (int c = 0; c < CHUNKS; ++c) {
        if (c + 1 < CHUNKS) {
            FILL_STAGE(((c + 1) & 1) * STAGEB, (size_t)(c + 1) * BK);
            CP_WAIT1();
        } else {
            CP_WAIT0();
        }
        __syncthreads();

        uint32_t stage = sb + SM_TILES + (uint32_t)(c & 1) * STAGEB;
        uint32_t Aw = stage + a_warp;
        uint32_t Bw = stage + TILEB + b_warp;

#pragma unroll
        for (int s = 0; s < 4; s++) {
            uint32_t kb = (uint32_t)(s * 32);   // 16 fp16 = 32 bytes

            uint32_t a[4][4], b[2][4];
#pragma unroll
            for (int mt = 0; mt < 4; mt++)
                ldsm_x4(Aw + (uint32_t)(mt * 16) * ROWB + kb,
                        a[mt][0], a[mt][1], a[mt][2], a[mt][3]);
#pragma unroll
            for (int n2 = 0; n2 < 2; n2++)
                ldsm_x4(Bw + (uint32_t)(n2 * 16) * ROWB + kb,
                        b[n2][0], b[n2][1], b[n2][2], b[n2][3]);
#pragma unroll
            for (int mt = 0; mt < 4; mt++)
#pragma unroll
                for (int nt = 0; nt < 4; nt++)
                    mma16816(acc[mt][nt], a[mt][0], a[mt][1], a[mt][2], a[mt][3],
                             b[nt >> 1][(nt & 1) * 2], b[nt >> 1][(nt & 1) * 2 + 1]);
        }
        __syncthreads();
    }

    // ---- epilogue ----
    int qrow = lane >> 2;          // 0..7
    int qcol = (lane & 3) * 2;     // 0,2,4,6
    float2 bias2[4];
#pragma unroll
    for (int nt = 0; nt < 4; nt++) {
        int nc = n0 + wn * 32 + nt * 8 + qcol;
        bias2[nt] = make_float2(be[e * FF + nc], be[e * FF + nc + 1]);
    }
#pragma unroll
    for (int mt = 0; mt < 4; mt++) {
#pragma unroll
        for (int half = 0; half < 2; half++) {
            int mrow = wm * 64 + mt * 16 + half * 8 + qrow;
            if (m0 + mrow < cnt) {
                int entry = s_entry[mrow];
                int tok   = entry & 0xFFFF;
                int slot  = entry >> 16;
                float w   = s_w[mrow];
#pragma unroll
                for (int nt = 0; nt < 4; nt++) {
                    int nc = n0 + wn * 32 + nt * 8 + qcol;
                    float2 o;
                    o.x = (acc[mt][nt][half * 2 + 0] + bias2[nt].x) * w;
                    o.y = (acc[mt][nt][half * 2 + 1] + bias2[nt].y) * w;
                    *(float2*)&g_scr[slot][tok][nc] = o;
                }
            }
        }
    }
}

// out = scr[0] + scr[1]
__global__ void combine_kernel(float* __restrict__ out) {
    size_t j = (size_t)blockIdx.x * blockDim.x + threadIdx.x;
    const float4* a = (const float4*)g_scr[0];
    const float4* b = (const float4*)g_scr[1];
    float4 u = a[j], v = b[j];
    ((float4*)out)[j] = make_float4(u.x + v.x, u.y + v.y, u.z + v.z, u.w + v.w);
}

extern "C" void kernel_launch(void* const* d_in, const int* in_sizes, int n_in,
                              void* d_out, int out_size) {
    const float* x  = (const float*)d_in[0];   // (4,4096,1024)
    const float* Wg = (const float*)d_in[1];   // (8,1024)
    const float* bg = (const float*)d_in[2];   // (8,)
    const float* We = (const float*)d_in[3];   // (8,1024,1024)
    const float* be = (const float*)d_in[4];   // (8,1024)
    float* out = (float*)d_out;                // (4,4096,1024) f32

    zero_cnt_kernel<<<1, 32>>>();
    gate_kernel<<<NT / 8, 256>>>(x, Wg, bg);

    split_transpose_We<<<dim3(DM / 32, FF / 32, NE), dim3(32, 8)>>>(We);

    cudaFuncSetAttribute(expert_gemm_tc, cudaFuncAttributeMaxDynamicSharedMemorySize, SM_TOTAL);
    expert_gemm_tc<<<dim3(NT / BM, FF / BN, NE), 256, SM_TOTAL>>>(be);

    combine_kernel<<<(NT * FF / 4) / 256, 256>>>(out);
}

// round 7
// speedup vs baseline: 9.7000x; 1.0761x over previous
#include <cuda_runtime.h>
#include <cuda_fp16.h>
#include <math.h>
#include <stdint.h>

#define NT 16384      // tokens = 4 * 4096
#define DM 1024       // d_model
#define FF 1024       // d_out
#define NE 8          // experts

// GEMM tiling
#define BM 128
#define BN 128
#define BK 32
#define CHUNKS (DM / BK)      // 32

// ---- device scratch (static, allocation-free) ----
__device__ int   g_cnt[NE];
__device__ int   g_list[NE][NT];        // packed: token | (slot<<16)
__device__ float g_w[2][NT];            // gate weight per slot per token
__device__ float g_scr[2][NT][FF];      // per-slot expert outputs (128 MiB)
__device__ __align__(16) __half g_xh[(size_t)NT * DM];          // fp16 x
__device__ __align__(16) __half g_wt[(size_t)NE * FF * DM];     // [e][n][k], fp16

// ======================= aux kernels =======================
__global__ void zero_cnt_kernel() {
    if (threadIdx.x < NE) g_cnt[threadIdx.x] = 0;
}

// One warp per token: 8 dots of length 1024, warp-reduce, top-2, sigmoid, scatter.
// Also emits fp16 x (x already in registers here).
__global__ void gate_kernel(const float* __restrict__ x,
                            const float* __restrict__ Wg,
                            const float* __restrict__ bg) {
    int gwarp = (blockIdx.x * blockDim.x + threadIdx.x) >> 5;
    int lane  = threadIdx.x & 31;
    if (gwarp >= NT) return;

    const float* xr = x + (size_t)gwarp * DM;
    float xv[32];
#pragma unroll
    for (int i = 0; i < 32; i++) xv[i] = xr[lane + 32 * i];

    __half* xh = g_xh + (size_t)gwarp * DM + lane;
#pragma unroll
    for (int i = 0; i < 32; i++) xh[32 * i] = __float2half_rn(xv[i]);

    float logits[NE];
#pragma unroll
    for (int e = 0; e < NE; e++) {
        const float* wg = Wg + e * DM;
        float acc = 0.f;
#pragma unroll
        for (int i = 0; i < 32; i++) acc += xv[i] * wg[lane + 32 * i];
#pragma unroll
        for (int o = 16; o > 0; o >>= 1) acc += __shfl_xor_sync(0xffffffffu, acc, o);
        logits[e] = acc + bg[e];
    }

    if (lane == 0) {
        int b0 = 0; float v0 = logits[0];
#pragma unroll
        for (int e = 1; e < NE; e++) if (logits[e] > v0) { v0 = logits[e]; b0 = e; }
        int b1 = -1; float v1 = -INFINITY;
#pragma unroll
        for (int e = 0; e < NE; e++) if (e != b0 && logits[e] > v1) { v1 = logits[e]; b1 = e; }

        g_w[0][gwarp] = 1.f / (1.f + expf(-v0));
        g_w[1][gwarp] = 1.f / (1.f + expf(-v1));

        int p0 = atomicAdd(&g_cnt[b0], 1);
        g_list[b0][p0] = gwarp;
        int p1 = atomicAdd(&g_cnt[b1], 1);
        g_list[b1][p1] = gwarp | (1 << 16);
    }
}

// We[e][k][n] -> WT[e][n][k] (transpose, fp16), 32x32 tiles.
__global__ void split_transpose_We(const float* __restrict__ We) {
    __shared__ float tile[32][33];
    int e  = blockIdx.z;
    int k0 = blockIdx.x * 32;
    int n0 = blockIdx.y * 32;
    int tx = threadIdx.x, ty = threadIdx.y;

    const float* src = We + ((size_t)e * DM) * FF;
#pragma unroll
    for (int i = ty; i < 32; i += 8)
        tile[i][tx] = src[(size_t)(k0 + i) * FF + n0 + tx];
    __syncthreads();
#pragma unroll
    for (int i = ty; i < 32; i += 8) {
        float v = tile[tx][i];  // = We[e][k0+tx][n0+i]
        size_t di = ((size_t)e * FF + (n0 + i)) * DM + k0 + tx;
        g_wt[di] = __float2half_rn(v);
    }
}

// ======================= HMMA expert GEMM =======================
// smem layout (bytes):
//   [0,512)    s_entry (128 int)
//   [512,1024) s_w     (128 float)
//   [1024, +4*20480) 4 stages; per stage A tile then B tile,
//   each 128 rows x 80B (64B data + 16B pad)
#define ROWB 80
#define TILEB (128 * ROWB)       // 10240
#define STAGEB (2 * TILEB)       // 20480
#define SM_TILES 1024
#define SM_TOTAL (SM_TILES + 4 * STAGEB)   // 82944

__device__ __forceinline__ uint32_t smem_u32(const void* p) {
    uint32_t a;
    asm("{ .reg .u64 t; cvta.to.shared.u64 t, %1; cvt.u32.u64 %0, t; }" : "=r"(a) : "l"(p));
    return a;
}
#define CP_ASYNC16(dst, src) \
    asm volatile("cp.async.cg.shared.global [%0], [%1], 16;" :: "r"(dst), "l"(src))
#define CP_COMMIT() asm volatile("cp.async.commit_group;")
#define CP_WAIT2()  asm volatile("cp.async.wait_group 2;")
#define CP_WAIT1()  asm volatile("cp.async.wait_group 1;")
#define CP_WAIT0()  asm volatile("cp.async.wait_group 0;")

__device__ __forceinline__ void ldsm_x4(uint32_t a, uint32_t& r0, uint32_t& r1,
                                        uint32_t& r2, uint32_t& r3) {
    asm volatile("ldmatrix.sync.aligned.m8n8.x4.shared.b16 {%0,%1,%2,%3}, [%4];"
                 : "=r"(r0), "=r"(r1), "=r"(r2), "=r"(r3) : "r"(a));
}
__device__ __forceinline__ void mma16816(float* c, uint32_t a0, uint32_t a1,
                                         uint32_t a2, uint32_t a3,
                                         uint32_t b0, uint32_t b1) {
    asm volatile(
        "mma.sync.aligned.m16n8k16.row.col.f32.f16.f16.f32 "
        "{%0,%1,%2,%3}, {%4,%5,%6,%7}, {%8,%9}, {%0,%1,%2,%3};"
        : "+f"(c[0]), "+f"(c[1]), "+f"(c[2]), "+f"(c[3])
        : "r"(a0), "r"(a1), "r"(a2), "r"(a3), "r"(b0), "r"(b1));
}

__global__ void __launch_bounds__(256, 2) expert_gemm_tc(const float* __restrict__ be) {
    extern __shared__ char smem[];
    int e   = blockIdx.z;
    int cnt = g_cnt[e];
    int m0  = blockIdx.x * BM;
    if (m0 >= cnt) return;
    int n0  = blockIdx.y * BN;

    int tid  = threadIdx.x;
    int wid  = tid >> 5;
    int lane = tid & 31;

    int*   s_entry = (int*)smem;
    float* s_w     = (float*)(smem + 512);

    // routing metadata for this row-block
    if (tid < BM) {
        int mi = m0 + tid;
        int entry = (mi < cnt) ? g_list[e][mi] : 0;
        s_entry[tid] = entry;
        s_w[tid]     = g_w[entry >> 16][entry & 0xFFFF];
    }
    __syncthreads();

    // ---- cp.async mapping: thread t covers row r = t>>1, 32B half h = t&1 of both tiles ----
    int r = tid >> 1;            // 0..127
    int h = tid & 1;             // 32B half of the 64B row
    size_t xbase = (size_t)(s_entry[r] & 0xFFFF) * DM + h * 16;
    size_t wbase = ((size_t)e * FF + n0 + r) * DM + h * 16;

    uint32_t sb  = smem_u32(smem);
    uint32_t dst = sb + SM_TILES + (uint32_t)(r * ROWB + h * 32);

#define FILL_STAGE(stoff, kelem) do {                                              \
        uint32_t d = (stoff);                                                      \
        const char* sa = (const char*)(g_xh + xbase + (kelem));                    \
        const char* sw = (const char*)(g_wt + wbase + (kelem));                    \
        CP_ASYNC16(dst + d,              sa);                                      \
        CP_ASYNC16(dst + d + 16,         sa + 16);                                 \
        CP_ASYNC16(dst + d + TILEB,      sw);                                      \
        CP_ASYNC16(dst + d + TILEB + 16, sw + 16);                                 \
        CP_COMMIT();                                                               \
    } while (0)

    // ---- ldmatrix per-lane offsets ----
    uint32_t a_lane = (uint32_t)((lane & 15) * ROWB + (lane >> 4) * 16);
    uint32_t b_lane = (uint32_t)(((lane >> 4) * 8 + (lane & 7)) * ROWB + ((lane >> 3) & 1) * 16);

    int wm = wid & 1;         // 2 warps in M
    int wn = wid >> 1;        // 4 warps in N
    uint32_t a_warp = a_lane + (uint32_t)(wm * 64) * ROWB;
    uint32_t b_warp = b_lane + (uint32_t)(wn * 32) * ROWB;

    float acc[4][4][4];
#pragma unroll
    for (int i = 0; i < 4; i++)
#pragma unroll
        for (int j = 0; j < 4; j++)
#pragma unroll
            for (int k = 0; k < 4; k++) acc[i][j][k] = 0.f;

    // prologue: stages 0..2 in flight
    FILL_STAGE(0, 0);
    FILL_STAGE(STAGEB, (size_t)BK);
    FILL_STAGE(2 * STAGEB, (size_t)(2 * BK));

    for (int c = 0; c < CHUNKS; ++c) {
        // wait until this chunk's fill has landed (cap by remaining groups)
        if (c <= CHUNKS - 3)      { CP_WAIT2(); }
        else if (c == CHUNKS - 2) { CP_WAIT1(); }
        else                      { CP_WAIT0(); }
        __syncthreads();                      // everyone sees stage c; stage c+3's slot is free
        if (c + 3 < CHUNKS)
            FILL_STAGE((uint32_t)((c + 3) & 3) * STAGEB, (size_t)(c + 3) * BK);

        uint32_t stage = sb + SM_TILES + (uint32_t)(c & 3) * STAGEB;
        uint32_t Aw = stage + a_warp;
        uint32_t Bw = stage + TILEB + b_warp;

#pragma unroll
        for (int s = 0; s < 2; s++) {
            uint32_t kb = (uint32_t)(s * 32);   // 16 fp16 = 32 bytes

            uint32_t a[4][4], b[2][4];
#pragma unroll
            for (int mt = 0; mt < 4; mt++)
                ldsm_x4(Aw + (uint32_t)(mt * 16) * ROWB + kb,
                        a[mt][0], a[mt][1], a[mt][2], a[mt][3]);
#pragma unroll
            for (int n2 = 0; n2 < 2; n2++)
                ldsm_x4(Bw + (uint32_t)(n2 * 16) * ROWB + kb,
                        b[n2][0], b[n2][1], b[n2][2], b[n2][3]);
#pragma unroll
            for (int mt = 0; mt < 4; mt++)
#pragma unroll
                for (int nt = 0; nt < 4; nt++)
                    mma16816(acc[mt][nt], a[mt][0], a[mt][1], a[mt][2], a[mt][3],
                             b[nt >> 1][(nt & 1) * 2], b[nt >> 1][(nt & 1) * 2 + 1]);
        }
    }

    // ---- epilogue ----
    int qrow = lane >> 2;          // 0..7
    int qcol = (lane & 3) * 2;     // 0,2,4,6
    float2 bias2[4];
#pragma unroll
    for (int nt = 0; nt < 4; nt++) {
        int nc = n0 + wn * 32 + nt * 8 + qcol;
        bias2[nt] = make_float2(be[e * FF + nc], be[e * FF + nc + 1]);
    }
#pragma unroll
    for (int mt = 0; mt < 4; mt++) {
#pragma unroll
        for (int half = 0; half < 2; half++) {
            int mrow = wm * 64 + mt * 16 + half * 8 + qrow;
            if (m0 + mrow < cnt) {
                int entry = s_entry[mrow];
                int tok   = entry & 0xFFFF;
                int slot  = entry >> 16;
                float w   = s_w[mrow];
#pragma unroll
                for (int nt = 0; nt < 4; nt++) {
                    int nc = n0 + wn * 32 + nt * 8 + qcol;
                    float2 o;
                    o.x = (acc[mt][nt][half * 2 + 0] + bias2[nt].x) * w;
                    o.y = (acc[mt][nt][half * 2 + 1] + bias2[nt].y) * w;
                    *(float2*)&g_scr[slot][tok][nc] = o;
                }
            }
        }
    }
}

// out = scr[0] + scr[1]
__global__ void combine_kernel(float* __restrict__ out) {
    size_t j = (size_t)blockIdx.x * blockDim.x + threadIdx.x;
    const float4* a = (const float4*)g_scr[0];
    const float4* b = (const float4*)g_scr[1];
    float4 u = a[j], v = b[j];
    ((float4*)out)[j] = make_float4(u.x + v.x, u.y + v.y, u.z + v.z, u.w + v.w);
}

extern "C" void kernel_launch(void* const* d_in, const int* in_sizes, int n_in,
                              void* d_out, int out_size) {
    const float* x  = (const float*)d_in[0];   // (4,4096,1024)
    const float* Wg = (const float*)d_in[1];   // (8,1024)
    const float* bg = (const float*)d_in[2];   // (8,)
    const float* We = (const float*)d_in[3];   // (8,1024,1024)
    const float* be = (const float*)d_in[4];   // (8,1024)
    float* out = (float*)d_out;                // (4,4096,1024) f32

    zero_cnt_kernel<<<1, 32>>>();
    gate_kernel<<<NT / 8, 256>>>(x, Wg, bg);

    split_transpose_We<<<dim3(DM / 32, FF / 32, NE), dim3(32, 8)>>>(We);

    cudaFuncSetAttribute(expert_gemm_tc, cudaFuncAttributeMaxDynamicSharedMemorySize, SM_TOTAL);
    expert_gemm_tc<<<dim3(NT / BM, FF / BN, NE), 256, SM_TOTAL>>>(be);

    combine_kernel<<<(NT * FF / 4) / 256, 256>>>(out);
}

// round 8
// speedup vs baseline: 10.0352x; 1.0346x over previous
#include <cuda_runtime.h>
#include <cuda_fp16.h>
#include <math.h>
#include <stdint.h>

#define NT 16384      // tokens = 4 * 4096
#define DM 1024       // d_model
#define FF 1024       // d_out
#define NE 8          // experts

// GEMM tiling
#define BM 128
#define BN 256
#define BK 32
#define CHUNKS (DM / BK)      // 32

// ---- device scratch (static, allocation-free) ----
__device__ int   g_cnt[NE];
__device__ int   g_list[NE][NT];        // packed: token | (slot<<16)
__device__ float g_w[2][NT];            // gate weight per slot per token
__device__ float g_scr[2][NT][FF];      // per-slot expert outputs (128 MiB)
__device__ __align__(16) __half g_xh[(size_t)NT * DM];          // fp16 x
__device__ __align__(16) __half g_wt[(size_t)NE * FF * DM];     // [e][n][k], fp16

// ======================= aux kernels =======================
__global__ void zero_cnt_kernel() {
    if (threadIdx.x < NE) g_cnt[threadIdx.x] = 0;
}

// One warp per token: 8 dots of length 1024, warp-reduce, top-2, sigmoid, scatter.
// Also emits fp16 x (x already in registers here).
__global__ void gate_kernel(const float* __restrict__ x,
                            const float* __restrict__ Wg,
                            const float* __restrict__ bg) {
    int gwarp = (blockIdx.x * blockDim.x + threadIdx.x) >> 5;
    int lane  = threadIdx.x & 31;
    if (gwarp >= NT) return;

    const float* xr = x + (size_t)gwarp * DM;
    float xv[32];
#pragma unroll
    for (int i = 0; i < 32; i++) xv[i] = xr[lane + 32 * i];

    __half* xh = g_xh + (size_t)gwarp * DM + lane;
#pragma unroll
    for (int i = 0; i < 32; i++) xh[32 * i] = __float2half_rn(xv[i]);

    float logits[NE];
#pragma unroll
    for (int e = 0; e < NE; e++) {
        const float* wg = Wg + e * DM;
        float acc = 0.f;
#pragma unroll
        for (int i = 0; i < 32; i++) acc += xv[i] * wg[lane + 32 * i];
#pragma unroll
        for (int o = 16; o > 0; o >>= 1) acc += __shfl_xor_sync(0xffffffffu, acc, o);
        logits[e] = acc + bg[e];
    }

    if (lane == 0) {
        int b0 = 0; float v0 = logits[0];
#pragma unroll
        for (int e = 1; e < NE; e++) if (logits[e] > v0) { v0 = logits[e]; b0 = e; }
        int b1 = -1; float v1 = -INFINITY;
#pragma unroll
        for (int e = 0; e < NE; e++) if (e != b0 && logits[e] > v1) { v1 = logits[e]; b1 = e; }

        g_w[0][gwarp] = 1.f / (1.f + expf(-v0));
        g_w[1][gwarp] = 1.f / (1.f + expf(-v1));

        int p0 = atomicAdd(&g_cnt[b0], 1);
        g_list[b0][p0] = gwarp;
        int p1 = atomicAdd(&g_cnt[b1], 1);
        g_list[b1][p1] = gwarp | (1 << 16);
    }
}

// We[e][k][n] -> WT[e][n][k] (transpose, fp16), 32x32 tiles.
__global__ void split_transpose_We(const float* __restrict__ We) {
    __shared__ float tile[32][33];
    int e  = blockIdx.z;
    int k0 = blockIdx.x * 32;
    int n0 = blockIdx.y * 32;
    int tx = threadIdx.x, ty = threadIdx.y;

    const float* src = We + ((size_t)e * DM) * FF;
#pragma unroll
    for (int i = ty; i < 32; i += 8)
        tile[i][tx] = src[(size_t)(k0 + i) * FF + n0 + tx];
    __syncthreads();
#pragma unroll
    for (int i = ty; i < 32; i += 8) {
        float v = tile[tx][i];  // = We[e][k0+tx][n0+i]
        size_t di = ((size_t)e * FF + (n0 + i)) * DM + k0 + tx;
        g_wt[di] = __float2half_rn(v);
    }
}

// ======================= HMMA expert GEMM =======================
// smem layout (bytes):
//   [0,512)    s_entry (128 int)
//   [512,1024) s_w     (128 float)
//   [1024, +4*30720) 4 stages; per stage: A rows 0..127 then B rows 0..255,
//   each row 80B (64B data + 16B pad)
#define ROWB 80
#define ATILEB (128 * ROWB)      // 10240
#define STAGEB (384 * ROWB)      // 30720 (A 128 rows + B 256 rows)
#define SM_TILES 1024
#define SM_TOTAL (SM_TILES + 4 * STAGEB)   // 123904

__device__ __forceinline__ uint32_t smem_u32(const void* p) {
    uint32_t a;
    asm("{ .reg .u64 t; cvta.to.shared.u64 t, %1; cvt.u32.u64 %0, t; }" : "=r"(a) : "l"(p));
    return a;
}
#define CP_ASYNC16(dst, src) \
    asm volatile("cp.async.cg.shared.global [%0], [%1], 16;" :: "r"(dst), "l"(src))
#define CP_COMMIT() asm volatile("cp.async.commit_group;")
#define CP_WAIT2()  asm volatile("cp.async.wait_group 2;")
#define CP_WAIT1()  asm volatile("cp.async.wait_group 1;")
#define CP_WAIT0()  asm volatile("cp.async.wait_group 0;")

__device__ __forceinline__ void ldsm_x4(uint32_t a, uint32_t& r0, uint32_t& r1,
                                        uint32_t& r2, uint32_t& r3) {
    asm volatile("ldmatrix.sync.aligned.m8n8.x4.shared.b16 {%0,%1,%2,%3}, [%4];"
                 : "=r"(r0), "=r"(r1), "=r"(r2), "=r"(r3) : "r"(a));
}
__device__ __forceinline__ void mma16816(float* c, uint32_t a0, uint32_t a1,
                                         uint32_t a2, uint32_t a3,
                                         uint32_t b0, uint32_t b1) {
    asm volatile(
        "mma.sync.aligned.m16n8k16.row.col.f32.f16.f16.f32 "
        "{%0,%1,%2,%3}, {%4,%5,%6,%7}, {%8,%9}, {%0,%1,%2,%3};"
        : "+f"(c[0]), "+f"(c[1]), "+f"(c[2]), "+f"(c[3])
        : "r"(a0), "r"(a1), "r"(a2), "r"(a3), "r"(b0), "r"(b1));
}

__global__ void __launch_bounds__(256) expert_gemm_tc(const float* __restrict__ be) {
    extern __shared__ char smem[];
    int e   = blockIdx.z;
    int cnt = g_cnt[e];
    int m0  = blockIdx.x * BM;
    if (m0 >= cnt) return;
    int n0  = blockIdx.y * BN;

    int tid  = threadIdx.x;
    int wid  = tid >> 5;
    int lane = tid & 31;

    int*   s_entry = (int*)smem;
    float* s_w     = (float*)(smem + 512);

    // routing metadata for this row-block
    if (tid < BM) {
        int mi = m0 + tid;
        int entry = (mi < cnt) ? g_list[e][mi] : 0;
        s_entry[tid] = entry;
        s_w[tid]     = g_w[entry >> 16][entry & 0xFFFF];
    }
    __syncthreads();

    // ---- cp.async mapping: 1536 granules of 16B per stage (384 rows x 4) ----
    // granule g = i*256 + tid; row = g>>2 (0..127 A, 128..383 B), q = g&3
    const char* src6[6];
    uint32_t    dst6[6];
    uint32_t sb = smem_u32(smem);
#pragma unroll
    for (int i = 0; i < 6; i++) {
        int g   = i * 256 + tid;
        int row = g >> 2;
        int q   = g & 3;
        const __half* base;
        if (row < 128) {
            base = g_xh + (size_t)(s_entry[row] & 0xFFFF) * DM;
        } else {
            base = g_wt + ((size_t)e * FF + n0 + (row - 128)) * DM;
        }
        src6[i] = (const char*)(base + q * 8);
        dst6[i] = sb + SM_TILES + (uint32_t)(row * ROWB + q * 16);
    }

#define FILL_STAGE(stoff, kbytes) do {                                             \
        uint32_t d = (stoff);                                                      \
        CP_ASYNC16(dst6[0] + d, src6[0] + (kbytes));                               \
        CP_ASYNC16(dst6[1] + d, src6[1] + (kbytes));                               \
        CP_ASYNC16(dst6[2] + d, src6[2] + (kbytes));                               \
        CP_ASYNC16(dst6[3] + d, src6[3] + (kbytes));                               \
        CP_ASYNC16(dst6[4] + d, src6[4] + (kbytes));                               \
        CP_ASYNC16(dst6[5] + d, src6[5] + (kbytes));                               \
        CP_COMMIT();                                                               \
    } while (0)

    // ---- ldmatrix per-lane offsets ----
    uint32_t a_lane = (uint32_t)((lane & 15) * ROWB + (lane >> 4) * 16);
    uint32_t b_lane = (uint32_t)(((lane >> 4) * 8 + (lane & 7)) * ROWB + ((lane >> 3) & 1) * 16);

    int wm = wid & 1;         // 2 warps in M (64 rows each)
    int wn = wid >> 1;        // 4 warps in N (64 cols each)
    uint32_t a_warp = a_lane + (uint32_t)(wm * 64) * ROWB;
    uint32_t b_warp = b_lane + (uint32_t)(wn * 64) * ROWB + ATILEB;

    float acc[4][8][4];
#pragma unroll
    for (int i = 0; i < 4; i++)
#pragma unroll
        for (int j = 0; j < 8; j++)
#pragma unroll
            for (int k = 0; k < 4; k++) acc[i][j][k] = 0.f;

    // prologue: stages 0..2 in flight
    FILL_STAGE(0, 0);
    FILL_STAGE(STAGEB, BK * 2);
    FILL_STAGE(2 * STAGEB, 2 * BK * 2);

    for (int c = 0; c < CHUNKS; ++c) {
        if (c <= CHUNKS - 3)      { CP_WAIT2(); }
        else if (c == CHUNKS - 2) { CP_WAIT1(); }
        else                      { CP_WAIT0(); }
        __syncthreads();
        if (c + 3 < CHUNKS)
            FILL_STAGE((uint32_t)((c + 3) & 3) * STAGEB, (c + 3) * BK * 2);

        uint32_t stage = sb + SM_TILES + (uint32_t)(c & 3) * STAGEB;
        uint32_t Aw = stage + a_warp;
        uint32_t Bw = stage + b_warp;

#pragma unroll
        for (int s = 0; s < 2; s++) {
            uint32_t kb = (uint32_t)(s * 32);   // 16 fp16 = 32 bytes

            uint32_t a[4][4], b[4][4];
#pragma unroll
            for (int mt = 0; mt < 4; mt++)
                ldsm_x4(Aw + (uint32_t)(mt * 16) * ROWB + kb,
                        a[mt][0], a[mt][1], a[mt][2], a[mt][3]);
#pragma unroll
            for (int n2 = 0; n2 < 4; n2++)
                ldsm_x4(Bw + (uint32_t)(n2 * 16) * ROWB + kb,
                        b[n2][0], b[n2][1], b[n2][2], b[n2][3]);
#pragma unroll
            for (int mt = 0; mt < 4; mt++)
#pragma unroll
                for (int n2 = 0; n2 < 4; n2++) {
                    mma16816(acc[mt][n2 * 2 + 0], a[mt][0], a[mt][1], a[mt][2], a[mt][3],
                             b[n2][0], b[n2][1]);
                    mma16816(acc[mt][n2 * 2 + 1], a[mt][0], a[mt][1], a[mt][2], a[mt][3],
                             b[n2][2], b[n2][3]);
                }
        }
    }

    // ---- epilogue ----
    int qrow = lane >> 2;          // 0..7
    int qcol = (lane & 3) * 2;     // 0,2,4,6
    float2 bias2[8];
#pragma unroll
    for (int nt = 0; nt < 8; nt++) {
        int nc = n0 + wn * 64 + nt * 8 + qcol;
        bias2[nt] = make_float2(be[e * FF + nc], be[e * FF + nc + 1]);
    }
#pragma unroll
    for (int mt = 0; mt < 4; mt++) {
#pragma unroll
        for (int half = 0; half < 2; half++) {
            int mrow = wm * 64 + mt * 16 + half * 8 + qrow;
            if (m0 + mrow < cnt) {
                int entry = s_entry[mrow];
                int tok   = entry & 0xFFFF;
                int slot  = entry >> 16;
                float w   = s_w[mrow];
#pragma unroll
                for (int nt = 0; nt < 8; nt++) {
                    int nc = n0 + wn * 64 + nt * 8 + qcol;
                    float2 o;
                    o.x = (acc[mt][nt][half * 2 + 0] + bias2[nt].x) * w;
                    o.y = (acc[mt][nt][half * 2 + 1] + bias2[nt].y) * w;
                    *(float2*)&g_scr[slot][tok][nc] = o;
                }
            }
        }
    }
}

// out = scr[0] + scr[1]
__global__ void combine_kernel(float* __restrict__ out) {
    size_t j = (size_t)blockIdx.x * blockDim.x + threadIdx.x;
    const float4* a = (const float4*)g_scr[0];
    const float4* b = (const float4*)g_scr[1];
    float4 u = a[j], v = b[j];
    ((float4*)out)[j] = make_float4(u.x + v.x, u.y + v.y, u.z + v.z, u.w + v.w);
}

extern "C" void kernel_launch(void* const* d_in, const int* in_sizes, int n_in,
                              void* d_out, int out_size) {
    const float* x  = (const float*)d_in[0];   // (4,4096,1024)
    const float* Wg = (const float*)d_in[1];   // (8,1024)
    const float* bg = (const float*)d_in[2];   // (8,)
    const float* We = (const float*)d_in[3];   // (8,1024,1024)
    const float* be = (const float*)d_in[4];   // (8,1024)
    float* out = (float*)d_out;                // (4,4096,1024) f32

    zero_cnt_kernel<<<1, 32>>>();
    gate_kernel<<<NT / 8, 256>>>(x, Wg, bg);

    split_transpose_We<<<dim3(DM / 32, FF / 32, NE), dim3(32, 8)>>>(We);

    cudaFuncSetAttribute(expert_gemm_tc, cudaFuncAttributeMaxDynamicSharedMemorySize, SM_TOTAL);
    expert_gemm_tc<<<dim3(NT / BM, FF / BN, NE), 256, SM_TOTAL>>>(be);

    combine_kernel<<<(NT * FF / 4) / 256, 256>>>(out);
}